// round 16
// baseline (speedup 1.0000x reference)
#include <cuda_runtime.h>
#include <cuda_bf16.h>
#include <cstdint>

// Problem constants (fixed-shape problem)
#define Bn 16
#define Nn 10000
#define Tn 24
#define Hn 32
#define On 16
#define Mn (Bn*Nn)          // 160000 rows
#define G3H 96              // 3*H
#define En 160000           // edge count (fixed-shape)

// ---------------- device scratch (no allocations allowed) ----------------
__device__ float g_xw1 [Mn*Hn];   // conv1 x@W1,   [n][b][32]
__device__ float g_out1[Mn*Hn];   // conv1 result, [n][b][32]
__device__ float g_xw2 [Mn*On];   // conv2 x@W2,   [n][b][16]
__device__ float g_out2[Mn*On];   // conv2 result, [n][b][16]
__device__ float g_deg [Nn];
__device__ float g_dinv[Nn];
// CSR (reverse adjacency by target node)
__device__ int   g_cnt [Nn];
__device__ int   g_ofs [Nn];
__device__ int   g_pos [Nn];
__device__ int   g_eid [En];

// ---------------- helpers ----------------
__device__ __forceinline__ float tanhap(float x){
    float y;
    asm("tanh.approx.f32 %0, %1;" : "=f"(y) : "f"(x));
    return y;
}
__device__ __forceinline__ uint32_t pack_bf2(__nv_bfloat16 lo, __nv_bfloat16 hi){
    __nv_bfloat162 t = __halves2bfloat162(lo, hi);   // .x -> low 16 bits
    return *reinterpret_cast<uint32_t*>(&t);
}
// split two floats into packed bf16 hi + residual lo
__device__ __forceinline__ void split2(float a, float b, uint32_t& hi, uint32_t& lo){
    __nv_bfloat16 ah = __float2bfloat16(a), bh = __float2bfloat16(b);
    hi = pack_bf2(ah, bh);
    lo = pack_bf2(__float2bfloat16(a - __bfloat162float(ah)),
                  __float2bfloat16(b - __bfloat162float(bh)));
}
__device__ __forceinline__ void mma_bf16(float* d, const uint32_t* a, uint32_t b0, uint32_t b1){
    asm volatile("mma.sync.aligned.m16n8k16.row.col.f32.bf16.bf16.f32 "
        "{%0,%1,%2,%3}, {%4,%5,%6,%7}, {%8,%9}, {%0,%1,%2,%3};"
        : "+f"(d[0]),"+f"(d[1]),"+f"(d[2]),"+f"(d[3])
        : "r"(a[0]),"r"(a[1]),"r"(a[2]),"r"(a[3]), "r"(b0),"r"(b1));
}

// ---------------- degree / norm / CSR build ----------------
__global__ void init_kernel(){
    int i = blockIdx.x*blockDim.x + threadIdx.x;
    if (i < Nn){ g_deg[i] = 1.f; g_cnt[i] = 0; }   // deg starts at self-loop weight
}
__global__ void edge_acc_kernel(const int* __restrict__ ei,
                                const float* __restrict__ ew, int E){
    int e = blockIdx.x*blockDim.x + threadIdx.x;
    if (e < E){
        int t = ei[E + e];
        atomicAdd(&g_deg[t], ew[e]);
        atomicAdd(&g_cnt[t], 1);
    }
}
__global__ void dinv_kernel(){
    int i = blockIdx.x*blockDim.x + threadIdx.x;
    if (i < Nn){
        float d = g_deg[i];
        g_dinv[i] = d > 0.f ? rsqrtf(d) : 0.f;
    }
}
// single-block exclusive scan of g_cnt -> g_ofs (and g_pos cursor copy)
__global__ __launch_bounds__(1024) void scan_kernel(){
    __shared__ int part[1024];
    const int tid = threadIdx.x;
    const int base = tid*10;                 // 1024*10 >= Nn
    int loc[10]; int s = 0;
#pragma unroll
    for (int i = 0; i < 10; i++){
        int idx = base + i;
        int v = (idx < Nn) ? g_cnt[idx] : 0;
        loc[i] = s; s += v;
    }
    part[tid] = s;
    __syncthreads();
    for (int off = 1; off < 1024; off <<= 1){
        int v = (tid >= off) ? part[tid - off] : 0;
        __syncthreads();
        part[tid] += v;
        __syncthreads();
    }
    int pre = (tid > 0) ? part[tid-1] : 0;
#pragma unroll
    for (int i = 0; i < 10; i++){
        int idx = base + i;
        if (idx < Nn){ g_ofs[idx] = pre + loc[i]; g_pos[idx] = pre + loc[i]; }
    }
}
__global__ void fill_kernel(const int* __restrict__ ei, int E){
    int e = blockIdx.x*blockDim.x + threadIdx.x;
    if (e < E){
        int t = ei[E + e];
        int p = atomicAdd(&g_pos[t], 1);
        g_eid[p] = e;
    }
}

// ---------------- GRU via warp-level mma.sync (bf16 hi/lo split) ----------------
// Hot loop identical to R12/R15; 64-thr blocks x 7/SM -> 14 warps/SM.
// Epilogue fuses conv1's dense matmul (xw1 = h@W1); out1 init moved to gather.
__device__ __forceinline__ float bval(int nt, int k, int gcol, const float* w_hh){
    int gate = nt >> 2;
    int u = (nt & 3)*8 + gcol;
    return w_hh[(gate*32 + u)*32 + k];
}

#define GRU_TPB 64
#define WPB     2

__global__ __launch_bounds__(GRU_TPB,7)
void gru_mma_kernel(const float* __restrict__ x,
                    const float* __restrict__ w_ih, const float* __restrict__ w_hh,
                    const float* __restrict__ b_ih, const float* __restrict__ b_hh,
                    const float* __restrict__ W1)
{
    // B fragments: [tile][ktile][split][reg][lane]  (12 h-tiles, 2 k-tiles)
    __shared__ uint32_t sB[12][2][2][2][32];
    // per-unit gate constants: sc4[2u]=(wir,wiz,win,bR), sc4[2u+1]=(bZ,bhn,bxn,0)
    __shared__ float4 sc4[64];
    // W1 fragments for the fused conv1 matmul: [tile][ktile][lane]=(h0,h1,l0,l1)
    __shared__ uint4 sW1[4][2][32];

    const int tid  = threadIdx.x;
    const int lane = tid & 31;
    const int wid  = tid >> 5;
    const int g    = lane >> 2;      // fragment group (row / B n-col)
    const int tig  = lane & 3;       // thread in group

    // ---- one-time B fragment staging (h-part only) ----
    for (int i = tid; i < 12*2*2*2*32; i += GRU_TPB){
        int nt  = i >> 8;            // /256
        int rem = i & 255;
        int kt  = rem >> 7;          // /128
        int r   = (rem >> 5) & 1;    // reg
        int ln  = i & 31;
        int gg = ln >> 2, tg = ln & 3;
        int k0 = 16*kt + 2*tg + 8*r;
        float v0 = bval(nt, k0,   gg, w_hh);
        float v1 = bval(nt, k0+1, gg, w_hh);
        uint32_t hi, lo;
        split2(v0, v1, hi, lo);
        sB[nt][kt][0][r][ln] = hi;
        sB[nt][kt][1][r][ln] = lo;
    }
    // ---- one-time gate-constant staging ----
    if (tid < 64){
        int u = tid >> 1;
        if ((tid & 1) == 0)
            sc4[tid] = make_float4(w_ih[u], w_ih[32+u], w_ih[64+u], b_ih[u] + b_hh[u]);
        else
            sc4[tid] = make_float4(b_ih[32+u] + b_hh[32+u], b_hh[64+u], b_ih[64+u], 0.f);
    }
    // ---- one-time W1 fragment staging (W1 stored [in=k][out=u]) ----
    for (int i = tid; i < 4*2*32; i += GRU_TPB){
        int nt = i >> 6;
        int kt = (i >> 5) & 1;
        int ln = i & 31;
        int gg = ln >> 2, tg = ln & 3;
        int u  = nt*8 + gg;
        uint32_t h0, l0, h1, l1;
        {   int k0 = 16*kt + 2*tg;
            split2(W1[k0*Hn + u], W1[(k0+1)*Hn + u], h0, l0); }
        {   int k0 = 16*kt + 2*tg + 8;
            split2(W1[k0*Hn + u], W1[(k0+1)*Hn + u], h1, l1); }
        sW1[nt][kt][ln] = make_uint4(h0, h1, l0, l1);
    }
    __syncthreads();

    const int m0 = blockIdx.x*(WPB*16) + wid*16;   // 5000 blocks * 2 warps * 16 seqs
    const float* xa = x + (size_t)(m0 + g    )*Tn;
    const float* xb = x + (size_t)(m0 + g + 8)*Tn;

    // h in D-fragment layout: h[nt][e], nt=0..3 (units 8nt+2tig+{0,1}; rows g,g+8)
    float h[4][4];
#pragma unroll
    for (int a = 0; a < 4; a++)
#pragma unroll
        for (int e = 0; e < 4; e++) h[a][e] = 0.f;

#pragma unroll 1
    for (int t = 0; t < Tn; t++){
        // ---- pack A fragments (hi/lo) from h (k = 0..31 only) ----
        uint32_t Ah[2][4], Al[2][4];
#pragma unroll
        for (int kt = 0; kt < 2; kt++){
            split2(h[2*kt  ][0], h[2*kt  ][1], Ah[kt][0], Al[kt][0]);
            split2(h[2*kt  ][2], h[2*kt  ][3], Ah[kt][1], Al[kt][1]);
            split2(h[2*kt+1][0], h[2*kt+1][1], Ah[kt][2], Al[kt][2]);
            split2(h[2*kt+1][2], h[2*kt+1][3], Ah[kt][3], Al[kt][3]);
        }

        // ---- D init: exact fp32 x/bias contribution (broadcast LDS) ----
        float xga = __ldg(xa + t);
        float xgb = __ldg(xb + t);
        float D[12][4], Xn[4][4];
#pragma unroll
        for (int nt = 0; nt < 4; nt++){
#pragma unroll
            for (int eo = 0; eo < 2; eo++){
                int u = 8*nt + 2*tig + eo;
                float4 c0 = sc4[2*u];       // wir,wiz,win,bR
                float4 c1 = sc4[2*u+1];     // bZ,bhn,bxn,-
                D [nt  ][eo  ] = fmaf(c0.x, xga, c0.w);
                D [nt  ][eo+2] = fmaf(c0.x, xgb, c0.w);
                D [nt+4][eo  ] = fmaf(c0.y, xga, c1.x);
                D [nt+4][eo+2] = fmaf(c0.y, xgb, c1.x);
                D [nt+8][eo  ] = c1.y;
                D [nt+8][eo+2] = c1.y;
                Xn[nt  ][eo  ] = fmaf(c0.z, xga, c1.z);
                Xn[nt  ][eo+2] = fmaf(c0.z, xgb, c1.z);
            }
        }

        // ---- MMAs: 12 tiles x 2 k-tiles x 3 split products, accumulate into D ----
#pragma unroll
        for (int nt = 0; nt < 12; nt++){
#pragma unroll
            for (int kt = 0; kt < 2; kt++){
                uint32_t bh0 = sB[nt][kt][0][0][lane], bh1 = sB[nt][kt][0][1][lane];
                uint32_t bl0 = sB[nt][kt][1][0][lane], bl1 = sB[nt][kt][1][1][lane];
                mma_bf16(D[nt], Ah[kt], bh0, bh1);
                mma_bf16(D[nt], Al[kt], bh0, bh1);
                mma_bf16(D[nt], Ah[kt], bl0, bl1);
            }
        }

        // ---- gates + state update (element-wise, same fragment positions) ----
#pragma unroll
        for (int nt = 0; nt < 4; nt++)
#pragma unroll
            for (int e = 0; e < 4; e++){
                float r  = fmaf(0.5f, tanhap(0.5f*D[nt  ][e]), 0.5f);
                float z  = fmaf(0.5f, tanhap(0.5f*D[nt+4][e]), 0.5f);
                float nv = tanhap(fmaf(r, D[nt+8][e], Xn[nt][e]));
                h[nt][e] = fmaf(z, h[nt][e] - nv, nv);
            }
    }

    // ======== fused conv1 dense matmul: xw1 = h @ W1 (once per warp) ========
    {
        uint32_t Ah[2][4], Al[2][4];
#pragma unroll
        for (int kt = 0; kt < 2; kt++){
            split2(h[2*kt  ][0], h[2*kt  ][1], Ah[kt][0], Al[kt][0]);
            split2(h[2*kt  ][2], h[2*kt  ][3], Ah[kt][1], Al[kt][1]);
            split2(h[2*kt+1][0], h[2*kt+1][1], Ah[kt][2], Al[kt][2]);
            split2(h[2*kt+1][2], h[2*kt+1][3], Ah[kt][3], Al[kt][3]);
        }
        float Dx[4][4];
#pragma unroll
        for (int nt = 0; nt < 4; nt++){
#pragma unroll
            for (int e = 0; e < 4; e++) Dx[nt][e] = 0.f;
#pragma unroll
            for (int kt = 0; kt < 2; kt++){
                uint4 bb = sW1[nt][kt][lane];
                mma_bf16(Dx[nt], Ah[kt], bb.x, bb.y);
                mma_bf16(Dx[nt], Al[kt], bb.x, bb.y);
                mma_bf16(Dx[nt], Ah[kt], bb.z, bb.w);
            }
        }
        int mA = m0 + g,      nnA = mA % Nn, bA = mA / Nn;
        int mB = m0 + g + 8,  nnB = mB % Nn, bB = mB / Nn;
        float* xwA = g_xw1 + ((size_t)nnA*Bn + bA)*Hn;
        float* xwB = g_xw1 + ((size_t)nnB*Bn + bB)*Hn;
#pragma unroll
        for (int nt = 0; nt < 4; nt++){
            int j0 = nt*8 + 2*tig;
            *(float2*)(xwA + j0) = make_float2(Dx[nt][0], Dx[nt][1]);
            *(float2*)(xwB + j0) = make_float2(Dx[nt][2], Dx[nt][3]);
        }
    }
}

// ---------------- dense matmul (+ bias+relu on input); writes xw only ----------------
template<int CIN, int COUT, bool RELU>
__global__ void mm_kernel(const float* __restrict__ in,
                          const float* __restrict__ W,
                          const float* __restrict__ bin,
                          float* __restrict__ xw)
{
    __shared__ float sW[CIN*COUT];
    __shared__ float sb[CIN];
    int tid = threadIdx.x;
    for (int i = tid; i < CIN*COUT; i += blockDim.x) sW[i] = W[i];
    if (RELU && tid < CIN) sb[tid] = bin[tid];
    __syncthreads();

    int r = blockIdx.x*blockDim.x + tid;
    if (r >= Mn) return;

    float v[CIN];
#pragma unroll
    for (int i = 0; i < CIN; i += 4){
        float4 t4 = *(const float4*)(in + (size_t)r*CIN + i);
        v[i]=t4.x; v[i+1]=t4.y; v[i+2]=t4.z; v[i+3]=t4.w;
    }
    if (RELU){
#pragma unroll
        for (int i = 0; i < CIN; i++) v[i] = fmaxf(v[i] + sb[i], 0.f);
    }
    float acc[COUT];
#pragma unroll
    for (int o = 0; o < COUT; o++) acc[o] = 0.f;
#pragma unroll
    for (int i = 0; i < CIN; i++){
        float vi = v[i];
#pragma unroll
        for (int o = 0; o < COUT; o++) acc[o] += vi * sW[i*COUT + o];
    }
    float* px = xw + (size_t)r*COUT;
#pragma unroll
    for (int o = 0; o < COUT; o += 4)
        *(float4*)(px+o) = make_float4(acc[o], acc[o+1], acc[o+2], acc[o+3]);
}

// ---------------- CSR gather: warp per node, register accumulation ----------------
template<int C>
__global__ void gather_kernel(const int* __restrict__ ei,
                              const float* __restrict__ ew,
                              const float* __restrict__ xw,
                              float* __restrict__ out, int E)
{
    int w    = (blockIdx.x*blockDim.x + threadIdx.x) >> 5;
    int lane = threadIdx.x & 31;
    if (w >= Nn) return;
    const int RB = (Bn*C)/128;              // float4 per lane

    float di = g_dinv[w];
    float dd = di*di;
    float4 acc[RB];
    const float4* self = (const float4*)(xw + (size_t)w*(Bn*C));
#pragma unroll
    for (int i = 0; i < RB; i++){
        float4 v = self[lane + 32*i];
        acc[i] = make_float4(dd*v.x, dd*v.y, dd*v.z, dd*v.w);
    }
    int start = g_ofs[w];
    int cnt   = g_cnt[w];
#pragma unroll 1
    for (int j = 0; j < cnt; j++){
        int e   = __ldg(g_eid + start + j);
        int src = __ldg(ei + e);
        float nrm = g_dinv[src] * __ldg(ew + e) * di;
        const float4* s = (const float4*)(xw + (size_t)src*(Bn*C));
#pragma unroll
        for (int i = 0; i < RB; i++){
            float4 v = s[lane + 32*i];
            acc[i].x = fmaf(nrm, v.x, acc[i].x);
            acc[i].y = fmaf(nrm, v.y, acc[i].y);
            acc[i].z = fmaf(nrm, v.z, acc[i].z);
            acc[i].w = fmaf(nrm, v.w, acc[i].w);
        }
    }
    float4* d = (float4*)(out + (size_t)w*(Bn*C));
#pragma unroll
    for (int i = 0; i < RB; i++) d[lane + 32*i] = acc[i];
}

// ---------------- final linear head + [b][n] transpose ----------------
__global__ void final_kernel(const float* __restrict__ b2,
                             const float* __restrict__ Wfc,
                             const float* __restrict__ bfc,
                             float* __restrict__ y)
{
    int r = blockIdx.x*blockDim.x + threadIdx.x;
    if (r >= Mn) return;
    int n = r / Bn, b = r % Bn;
    const float* row = g_out2 + (size_t)r*On;
    float acc = bfc[0];
#pragma unroll
    for (int o = 0; o < On; o++) acc += (row[o] + b2[o]) * Wfc[o];
    y[(size_t)b*Nn + n] = acc;
}

// ---------------- launch ----------------
extern "C" void kernel_launch(void* const* d_in, const int* in_sizes, int n_in,
                              void* d_out, int out_size)
{
    const float* x    = (const float*)d_in[0];
    const int*   ei   = (const int*)  d_in[1];
    const float* ew   = (const float*)d_in[2];
    const float* w_ih = (const float*)d_in[3];
    const float* w_hh = (const float*)d_in[4];
    const float* b_ih = (const float*)d_in[5];
    const float* b_hh = (const float*)d_in[6];
    const float* W1   = (const float*)d_in[7];
    const float* b1   = (const float*)d_in[8];
    const float* W2   = (const float*)d_in[9];
    const float* b2   = (const float*)d_in[10];
    const float* Wfc  = (const float*)d_in[11];
    const float* bfc  = (const float*)d_in[12];
    float* y = (float*)d_out;
    int E = in_sizes[2];

    // resolve __device__ scratch addresses (not an allocation)
    float *p_xw1, *p_out1, *p_xw2, *p_out2;
    cudaGetSymbolAddress((void**)&p_xw1,  g_xw1);
    cudaGetSymbolAddress((void**)&p_out1, g_out1);
    cudaGetSymbolAddress((void**)&p_xw2,  g_xw2);
    cudaGetSymbolAddress((void**)&p_out2, g_out2);

    // 1) gcn_norm + CSR build
    init_kernel     <<<(Nn+255)/256, 256>>>();
    edge_acc_kernel <<<(E +255)/256, 256>>>(ei, ew, E);
    dinv_kernel     <<<(Nn+255)/256, 256>>>();
    scan_kernel     <<<1, 1024>>>();
    fill_kernel     <<<(E +255)/256, 256>>>(ei, E);

    // 2) GRU temporal encoder + fused conv1 matmul (writes xw1)
    gru_mma_kernel<<<Mn/(WPB*16), GRU_TPB>>>(x, w_ih, w_hh, b_ih, b_hh, W1);

    // 3) conv1 aggregation: out1 = dd*xw1 + sum_in nrm*xw1[src]
    gather_kernel<Hn><<<((size_t)Nn*32 + 255)/256, 256>>>(ei, ew, p_xw1, p_out1, E);

    // 4) conv2: xw2 = relu(out1+b1)@W2, then aggregation
    mm_kernel<Hn, On, true><<<(Mn+127)/128, 128>>>(p_out1, W2, b1, p_xw2);
    gather_kernel<On><<<((size_t)Nn*32 + 255)/256, 256>>>(ei, ew, p_xw2, p_out2, E);

    // 5) head: (out2+b2)@Wfc + bfc, transpose to [b][n]
    final_kernel<<<(Mn+255)/256, 256>>>(b2, Wfc, bfc, y);
}

// round 17
// speedup vs baseline: 1.1710x; 1.1710x over previous
#include <cuda_runtime.h>
#include <cuda_bf16.h>
#include <cstdint>

// Problem constants (fixed-shape problem)
#define Bn 16
#define Nn 10000
#define Tn 24
#define Hn 32
#define On 16
#define Mn (Bn*Nn)          // 160000 rows
#define G3H 96              // 3*H
#define En 160000           // edge count (fixed-shape)

// ---------------- device scratch (no allocations allowed) ----------------
__device__ float g_xw1 [Mn*Hn];   // conv1 x@W1,   [n][b][32]
__device__ float g_out1[Mn*Hn];   // conv1 result, [n][b][32]
__device__ float g_xw2 [Mn*On];   // conv2 x@W2,   [n][b][16]
__device__ float g_out2[Mn*On];   // conv2 result, [n][b][16]
__device__ float g_deg [Nn];
__device__ float g_dinv[Nn];
// CSR (reverse adjacency by target node)
__device__ int   g_cnt [Nn];
__device__ int   g_ofs [Nn];
__device__ int   g_pos [Nn];
__device__ int   g_eid [En];

// ---------------- helpers ----------------
__device__ __forceinline__ float tanhap(float x){
    float y;
    asm("tanh.approx.f32 %0, %1;" : "=f"(y) : "f"(x));
    return y;
}
__device__ __forceinline__ uint32_t pack_bf2(__nv_bfloat16 lo, __nv_bfloat16 hi){
    __nv_bfloat162 t = __halves2bfloat162(lo, hi);   // .x -> low 16 bits
    return *reinterpret_cast<uint32_t*>(&t);
}
// split two floats into packed bf16 hi + residual lo
__device__ __forceinline__ void split2(float a, float b, uint32_t& hi, uint32_t& lo){
    __nv_bfloat16 ah = __float2bfloat16(a), bh = __float2bfloat16(b);
    hi = pack_bf2(ah, bh);
    lo = pack_bf2(__float2bfloat16(a - __bfloat162float(ah)),
                  __float2bfloat16(b - __bfloat162float(bh)));
}
__device__ __forceinline__ void mma_bf16(float* d, const uint32_t* a, uint32_t b0, uint32_t b1){
    asm volatile("mma.sync.aligned.m16n8k16.row.col.f32.bf16.bf16.f32 "
        "{%0,%1,%2,%3}, {%4,%5,%6,%7}, {%8,%9}, {%0,%1,%2,%3};"
        : "+f"(d[0]),"+f"(d[1]),"+f"(d[2]),"+f"(d[3])
        : "r"(a[0]),"r"(a[1]),"r"(a[2]),"r"(a[3]), "r"(b0),"r"(b1));
}

// ---------------- degree / norm / CSR build ----------------
__global__ void init_kernel(){
    int i = blockIdx.x*blockDim.x + threadIdx.x;
    if (i < Nn){ g_deg[i] = 1.f; g_cnt[i] = 0; }   // deg starts at self-loop weight
}
__global__ void edge_acc_kernel(const int* __restrict__ ei,
                                const float* __restrict__ ew, int E){
    int e = blockIdx.x*blockDim.x + threadIdx.x;
    if (e < E){
        int t = ei[E + e];
        atomicAdd(&g_deg[t], ew[e]);
        atomicAdd(&g_cnt[t], 1);
    }
}
__global__ void dinv_kernel(){
    int i = blockIdx.x*blockDim.x + threadIdx.x;
    if (i < Nn){
        float d = g_deg[i];
        g_dinv[i] = d > 0.f ? rsqrtf(d) : 0.f;
    }
}
// single-block exclusive scan of g_cnt -> g_ofs, g_pos (shfl-based, 2-level)
__global__ __launch_bounds__(1024) void scan_kernel(){
    __shared__ int wsum[32];
    const int tid  = threadIdx.x;
    const int lane = tid & 31;
    const int wrp  = tid >> 5;
    const int base = tid*10;                 // 1024*10 >= Nn
    int loc[10]; int s = 0;
#pragma unroll
    for (int i = 0; i < 10; i++){
        int idx = base + i;
        int v = (idx < Nn) ? g_cnt[idx] : 0;
        loc[i] = s; s += v;
    }
    // warp-inclusive scan of per-thread sums
    int inc = s;
#pragma unroll
    for (int off = 1; off < 32; off <<= 1){
        int v = __shfl_up_sync(0xffffffffu, inc, off);
        if (lane >= off) inc += v;
    }
    if (lane == 31) wsum[wrp] = inc;
    __syncthreads();
    if (wrp == 0){
        int v = (lane < 32) ? wsum[lane] : 0;
#pragma unroll
        for (int off = 1; off < 32; off <<= 1){
            int u = __shfl_up_sync(0xffffffffu, v, off);
            if (lane >= off) v += u;
        }
        wsum[lane] = v;
    }
    __syncthreads();
    int pre = inc - s + (wrp > 0 ? wsum[wrp-1] : 0);   // exclusive prefix for this thread
#pragma unroll
    for (int i = 0; i < 10; i++){
        int idx = base + i;
        if (idx < Nn){ g_ofs[idx] = pre + loc[i]; g_pos[idx] = pre + loc[i]; }
    }
}
__global__ void fill_kernel(const int* __restrict__ ei, int E){
    int e = blockIdx.x*blockDim.x + threadIdx.x;
    if (e < E){
        int t = ei[E + e];
        int p = atomicAdd(&g_pos[t], 1);
        g_eid[p] = e;
    }
}

// ---------------- GRU via warp-level mma.sync (bf16 hi/lo split) ----------------
// R15 shape: 128 threads, 3 blocks/SM. Epilogue fuses conv1 matmul (writes xw1).
__device__ __forceinline__ float bval(int nt, int k, int gcol, const float* w_hh){
    int gate = nt >> 2;
    int u = (nt & 3)*8 + gcol;
    return w_hh[(gate*32 + u)*32 + k];
}

__global__ __launch_bounds__(128,3)
void gru_mma_kernel(const float* __restrict__ x,
                    const float* __restrict__ w_ih, const float* __restrict__ w_hh,
                    const float* __restrict__ b_ih, const float* __restrict__ b_hh,
                    const float* __restrict__ W1)
{
    // B fragments: [tile][ktile][split][reg][lane]  (12 h-tiles, 2 k-tiles)
    __shared__ uint32_t sB[12][2][2][2][32];
    // per-unit gate constants: sc4[2u]=(wir,wiz,win,bR), sc4[2u+1]=(bZ,bhn,bxn,0)
    __shared__ float4 sc4[64];
    // W1 fragments for the fused conv1 matmul: [tile][ktile][lane]=(h0,h1,l0,l1)
    __shared__ uint4 sW1[4][2][32];

    const int tid  = threadIdx.x;
    const int lane = tid & 31;
    const int wid  = tid >> 5;
    const int g    = lane >> 2;      // fragment group (row / B n-col)
    const int tig  = lane & 3;       // thread in group

    // ---- one-time B fragment staging (h-part only) ----
    for (int i = tid; i < 12*2*2*2*32; i += 128){
        int nt  = i >> 8;            // /256
        int rem = i & 255;
        int kt  = rem >> 7;          // /128
        int r   = (rem >> 5) & 1;    // reg
        int ln  = i & 31;
        int gg = ln >> 2, tg = ln & 3;
        int k0 = 16*kt + 2*tg + 8*r;
        float v0 = bval(nt, k0,   gg, w_hh);
        float v1 = bval(nt, k0+1, gg, w_hh);
        uint32_t hi, lo;
        split2(v0, v1, hi, lo);
        sB[nt][kt][0][r][ln] = hi;
        sB[nt][kt][1][r][ln] = lo;
    }
    // ---- one-time gate-constant staging ----
    if (tid < 64){
        int u = tid >> 1;
        if ((tid & 1) == 0)
            sc4[tid] = make_float4(w_ih[u], w_ih[32+u], w_ih[64+u], b_ih[u] + b_hh[u]);
        else
            sc4[tid] = make_float4(b_ih[32+u] + b_hh[32+u], b_hh[64+u], b_ih[64+u], 0.f);
    }
    // ---- one-time W1 fragment staging (W1 stored [in=k][out=u]) ----
    for (int i = tid; i < 4*2*32; i += 128){
        int nt = i >> 6;
        int kt = (i >> 5) & 1;
        int ln = i & 31;
        int gg = ln >> 2, tg = ln & 3;
        int u  = nt*8 + gg;
        uint32_t h0, l0, h1, l1;
        {   int k0 = 16*kt + 2*tg;
            split2(W1[k0*Hn + u], W1[(k0+1)*Hn + u], h0, l0); }
        {   int k0 = 16*kt + 2*tg + 8;
            split2(W1[k0*Hn + u], W1[(k0+1)*Hn + u], h1, l1); }
        sW1[nt][kt][ln] = make_uint4(h0, h1, l0, l1);
    }
    __syncthreads();

    const int m0 = blockIdx.x*64 + wid*16;      // 2500 blocks * 4 warps * 16 seqs
    const float* xa = x + (size_t)(m0 + g    )*Tn;
    const float* xb = x + (size_t)(m0 + g + 8)*Tn;

    // h in D-fragment layout: h[nt][e], nt=0..3 (units 8nt+2tig+{0,1}; rows g,g+8)
    float h[4][4];
#pragma unroll
    for (int a = 0; a < 4; a++)
#pragma unroll
        for (int e = 0; e < 4; e++) h[a][e] = 0.f;

#pragma unroll 1
    for (int t = 0; t < Tn; t++){
        // ---- pack A fragments (hi/lo) from h (k = 0..31 only) ----
        uint32_t Ah[2][4], Al[2][4];
#pragma unroll
        for (int kt = 0; kt < 2; kt++){
            split2(h[2*kt  ][0], h[2*kt  ][1], Ah[kt][0], Al[kt][0]);
            split2(h[2*kt  ][2], h[2*kt  ][3], Ah[kt][1], Al[kt][1]);
            split2(h[2*kt+1][0], h[2*kt+1][1], Ah[kt][2], Al[kt][2]);
            split2(h[2*kt+1][2], h[2*kt+1][3], Ah[kt][3], Al[kt][3]);
        }

        // ---- D init: exact fp32 x/bias contribution (broadcast LDS) ----
        float xga = __ldg(xa + t);
        float xgb = __ldg(xb + t);
        float D[12][4], Xn[4][4];
#pragma unroll
        for (int nt = 0; nt < 4; nt++){
#pragma unroll
            for (int eo = 0; eo < 2; eo++){
                int u = 8*nt + 2*tig + eo;
                float4 c0 = sc4[2*u];       // wir,wiz,win,bR
                float4 c1 = sc4[2*u+1];     // bZ,bhn,bxn,-
                D [nt  ][eo  ] = fmaf(c0.x, xga, c0.w);
                D [nt  ][eo+2] = fmaf(c0.x, xgb, c0.w);
                D [nt+4][eo  ] = fmaf(c0.y, xga, c1.x);
                D [nt+4][eo+2] = fmaf(c0.y, xgb, c1.x);
                D [nt+8][eo  ] = c1.y;
                D [nt+8][eo+2] = c1.y;
                Xn[nt  ][eo  ] = fmaf(c0.z, xga, c1.z);
                Xn[nt  ][eo+2] = fmaf(c0.z, xgb, c1.z);
            }
        }

        // ---- MMAs: 12 tiles x 2 k-tiles x 3 split products, accumulate into D ----
#pragma unroll
        for (int nt = 0; nt < 12; nt++){
#pragma unroll
            for (int kt = 0; kt < 2; kt++){
                uint32_t bh0 = sB[nt][kt][0][0][lane], bh1 = sB[nt][kt][0][1][lane];
                uint32_t bl0 = sB[nt][kt][1][0][lane], bl1 = sB[nt][kt][1][1][lane];
                mma_bf16(D[nt], Ah[kt], bh0, bh1);
                mma_bf16(D[nt], Al[kt], bh0, bh1);
                mma_bf16(D[nt], Ah[kt], bl0, bl1);
            }
        }

        // ---- gates + state update (element-wise, same fragment positions) ----
#pragma unroll
        for (int nt = 0; nt < 4; nt++)
#pragma unroll
            for (int e = 0; e < 4; e++){
                float r  = fmaf(0.5f, tanhap(0.5f*D[nt  ][e]), 0.5f);
                float z  = fmaf(0.5f, tanhap(0.5f*D[nt+4][e]), 0.5f);
                float nv = tanhap(fmaf(r, D[nt+8][e], Xn[nt][e]));
                h[nt][e] = fmaf(z, h[nt][e] - nv, nv);
            }
    }

    // ======== fused conv1 dense matmul: xw1 = h @ W1 (once per warp) ========
    {
        uint32_t Ah[2][4], Al[2][4];
#pragma unroll
        for (int kt = 0; kt < 2; kt++){
            split2(h[2*kt  ][0], h[2*kt  ][1], Ah[kt][0], Al[kt][0]);
            split2(h[2*kt  ][2], h[2*kt  ][3], Ah[kt][1], Al[kt][1]);
            split2(h[2*kt+1][0], h[2*kt+1][1], Ah[kt][2], Al[kt][2]);
            split2(h[2*kt+1][2], h[2*kt+1][3], Ah[kt][3], Al[kt][3]);
        }
        float Dx[4][4];
#pragma unroll
        for (int nt = 0; nt < 4; nt++){
#pragma unroll
            for (int e = 0; e < 4; e++) Dx[nt][e] = 0.f;
#pragma unroll
            for (int kt = 0; kt < 2; kt++){
                uint4 bb = sW1[nt][kt][lane];
                mma_bf16(Dx[nt], Ah[kt], bb.x, bb.y);
                mma_bf16(Dx[nt], Al[kt], bb.x, bb.y);
                mma_bf16(Dx[nt], Ah[kt], bb.z, bb.w);
            }
        }
        int mA = m0 + g,      nnA = mA % Nn, bA = mA / Nn;
        int mB = m0 + g + 8,  nnB = mB % Nn, bB = mB / Nn;
        float* xwA = g_xw1 + ((size_t)nnA*Bn + bA)*Hn;
        float* xwB = g_xw1 + ((size_t)nnB*Bn + bB)*Hn;
#pragma unroll
        for (int nt = 0; nt < 4; nt++){
            int j0 = nt*8 + 2*tig;
            *(float2*)(xwA + j0) = make_float2(Dx[nt][0], Dx[nt][1]);
            *(float2*)(xwB + j0) = make_float2(Dx[nt][2], Dx[nt][3]);
        }
    }
}

// ---------------- dense matmul (+ bias+relu on input); writes xw only ----------------
template<int CIN, int COUT, bool RELU>
__global__ void mm_kernel(const float* __restrict__ in,
                          const float* __restrict__ W,
                          const float* __restrict__ bin,
                          float* __restrict__ xw)
{
    __shared__ float sW[CIN*COUT];
    __shared__ float sb[CIN];
    int tid = threadIdx.x;
    for (int i = tid; i < CIN*COUT; i += blockDim.x) sW[i] = W[i];
    if (RELU && tid < CIN) sb[tid] = bin[tid];
    __syncthreads();

    int r = blockIdx.x*blockDim.x + tid;
    if (r >= Mn) return;

    float v[CIN];
#pragma unroll
    for (int i = 0; i < CIN; i += 4){
        float4 t4 = *(const float4*)(in + (size_t)r*CIN + i);
        v[i]=t4.x; v[i+1]=t4.y; v[i+2]=t4.z; v[i+3]=t4.w;
    }
    if (RELU){
#pragma unroll
        for (int i = 0; i < CIN; i++) v[i] = fmaxf(v[i] + sb[i], 0.f);
    }
    float acc[COUT];
#pragma unroll
    for (int o = 0; o < COUT; o++) acc[o] = 0.f;
#pragma unroll
    for (int i = 0; i < CIN; i++){
        float vi = v[i];
#pragma unroll
        for (int o = 0; o < COUT; o++) acc[o] += vi * sW[i*COUT + o];
    }
    float* px = xw + (size_t)r*COUT;
#pragma unroll
    for (int o = 0; o < COUT; o += 4)
        *(float4*)(px+o) = make_float4(acc[o], acc[o+1], acc[o+2], acc[o+3]);
}

// ---------------- CSR gather: warp per node, register accumulation ----------------
template<int C>
__global__ void gather_kernel(const int* __restrict__ ei,
                              const float* __restrict__ ew,
                              const float* __restrict__ xw,
                              float* __restrict__ out, int E)
{
    int w    = (blockIdx.x*blockDim.x + threadIdx.x) >> 5;
    int lane = threadIdx.x & 31;
    if (w >= Nn) return;
    const int RB = (Bn*C)/128;              // float4 per lane

    float di = g_dinv[w];
    float dd = di*di;
    float4 acc[RB];
    const float4* self = (const float4*)(xw + (size_t)w*(Bn*C));
#pragma unroll
    for (int i = 0; i < RB; i++){
        float4 v = self[lane + 32*i];
        acc[i] = make_float4(dd*v.x, dd*v.y, dd*v.z, dd*v.w);
    }
    int start = g_ofs[w];
    int cnt   = g_cnt[w];
#pragma unroll 2
    for (int j = 0; j < cnt; j++){
        int e   = __ldg(g_eid + start + j);
        int src = __ldg(ei + e);
        float nrm = g_dinv[src] * __ldg(ew + e) * di;
        const float4* s = (const float4*)(xw + (size_t)src*(Bn*C));
#pragma unroll
        for (int i = 0; i < RB; i++){
            float4 v = s[lane + 32*i];
            acc[i].x = fmaf(nrm, v.x, acc[i].x);
            acc[i].y = fmaf(nrm, v.y, acc[i].y);
            acc[i].z = fmaf(nrm, v.z, acc[i].z);
            acc[i].w = fmaf(nrm, v.w, acc[i].w);
        }
    }
    float4* d = (float4*)(out + (size_t)w*(Bn*C));
#pragma unroll
    for (int i = 0; i < RB; i++) d[lane + 32*i] = acc[i];
}

// ---------------- final linear head + [b][n] transpose ----------------
__global__ void final_kernel(const float* __restrict__ b2,
                             const float* __restrict__ Wfc,
                             const float* __restrict__ bfc,
                             float* __restrict__ y)
{
    int r = blockIdx.x*blockDim.x + threadIdx.x;
    if (r >= Mn) return;
    int n = r / Bn, b = r % Bn;
    const float* row = g_out2 + (size_t)r*On;
    float acc = bfc[0];
#pragma unroll
    for (int o = 0; o < On; o++) acc += (row[o] + b2[o]) * Wfc[o];
    y[(size_t)b*Nn + n] = acc;
}

// ---------------- launch ----------------
extern "C" void kernel_launch(void* const* d_in, const int* in_sizes, int n_in,
                              void* d_out, int out_size)
{
    const float* x    = (const float*)d_in[0];
    const int*   ei   = (const int*)  d_in[1];
    const float* ew   = (const float*)d_in[2];
    const float* w_ih = (const float*)d_in[3];
    const float* w_hh = (const float*)d_in[4];
    const float* b_ih = (const float*)d_in[5];
    const float* b_hh = (const float*)d_in[6];
    const float* W1   = (const float*)d_in[7];
    const float* b1   = (const float*)d_in[8];
    const float* W2   = (const float*)d_in[9];
    const float* b2   = (const float*)d_in[10];
    const float* Wfc  = (const float*)d_in[11];
    const float* bfc  = (const float*)d_in[12];
    float* y = (float*)d_out;
    int E = in_sizes[2];

    // resolve __device__ scratch addresses (not an allocation)
    float *p_xw1, *p_out1, *p_xw2, *p_out2;
    cudaGetSymbolAddress((void**)&p_xw1,  g_xw1);
    cudaGetSymbolAddress((void**)&p_out1, g_out1);
    cudaGetSymbolAddress((void**)&p_xw2,  g_xw2);
    cudaGetSymbolAddress((void**)&p_out2, g_out2);

    // 1) gcn_norm + CSR build
    init_kernel     <<<(Nn+255)/256, 256>>>();
    edge_acc_kernel <<<(E +255)/256, 256>>>(ei, ew, E);
    dinv_kernel     <<<(Nn+255)/256, 256>>>();
    scan_kernel     <<<1, 1024>>>();
    fill_kernel     <<<(E +255)/256, 256>>>(ei, E);

    // 2) GRU temporal encoder + fused conv1 matmul (writes xw1) — R15 shape
    gru_mma_kernel<<<Mn/64, 128>>>(x, w_ih, w_hh, b_ih, b_hh, W1);

    // 3) conv1 aggregation: out1 = dd*xw1 + sum_in nrm*xw1[src]
    gather_kernel<Hn><<<((size_t)Nn*32 + 255)/256, 256>>>(ei, ew, p_xw1, p_out1, E);

    // 4) conv2: xw2 = relu(out1+b1)@W2, then aggregation
    mm_kernel<Hn, On, true><<<(Mn+127)/128, 128>>>(p_out1, W2, b1, p_xw2);
    gather_kernel<On><<<((size_t)Nn*32 + 255)/256, 256>>>(ei, ew, p_xw2, p_out2, E);

    // 5) head: (out2+b2)@Wfc + bfc, transpose to [b][n]
    final_kernel<<<(Mn+255)/256, 256>>>(b2, Wfc, bfc, y);
}